// round 15
// baseline (speedup 1.0000x reference)
#include <cuda_runtime.h>
#include <cuda_fp16.h>
#include <math.h>

// ---------------------------------------------------------------------------
// HierarchicalClustering via split-fp16 tensor-core GEMMs (mma.sync HMMA).
//   logits = 0.5*(h @ c^T) - 0.25*||c||^2   (||h||^2 cancels in softmax)
//   p      = softmax_rows(logits)
//   t      = tanh(h @ W^T + b)
//   h_next = p^T @ t = (e^{l-m})^T @ (t * sinv)
// fp16 pair-packed u32 operands [rows][K/2].
//   logits: (h_hi,h_lo)x(c_hi,c_lo) 3 MMAs
//   t     : (h_hi,h_lo)x(W_hi)      2 MMAs  (fork stream s2)
//   out   : e_hi x t_hi             1 MMA
// GEMM: 128x128 CTA tile, 8 warps of 64x32, 2 CTAs/SM, XOR-swizzled 64B smem
// rows, one __syncthreads per k-iter, mid-iteration prefetch.
// L1 logits GEMM split into 4 row chunks; softmax+scale chunks pipeline on a
// third stream s3 behind per-chunk events (rmax is chunk-final by design).
// ---------------------------------------------------------------------------

#define D 1024
#define N0 16384
#define N1 2048
#define N2 256
#define N3 32

__device__ float    g_G[(size_t)N0 * N1];
__device__ float    g_Hn[(size_t)N1 * D];
__device__ unsigned g_hPhi[(size_t)N0 * (D / 2)];
__device__ unsigned g_hPlo[(size_t)N0 * (D / 2)];
__device__ unsigned g_cPhi1[(size_t)N1 * (D / 2)];
__device__ unsigned g_cPlo1[(size_t)N1 * (D / 2)];
__device__ unsigned g_cPhi2[(size_t)N2 * (D / 2)];
__device__ unsigned g_cPlo2[(size_t)N2 * (D / 2)];
__device__ unsigned g_cPhi3[(size_t)N3 * (D / 2)];
__device__ unsigned g_cPlo3[(size_t)N3 * (D / 2)];
__device__ unsigned g_wPhi1[(size_t)D * (D / 2)];
__device__ unsigned g_wPhi2[(size_t)D * (D / 2)];
__device__ unsigned g_wPhi3[(size_t)D * (D / 2)];
__device__ unsigned g_GThi[(size_t)N1 * (N0 / 2)];
__device__ unsigned g_GTlo[(size_t)N1 * (N0 / 2)];
__device__ unsigned g_tT[(size_t)D * (N0 / 2)];
__device__ float    g_cnq1[N1];
__device__ float    g_cnq2[N2];
__device__ float    g_cnq3[N3];
__device__ unsigned g_rmax[N0];
__device__ float    g_sinv[N0];

// ------------------------------- helpers -----------------------------------
__device__ __forceinline__ unsigned h_bits(float v) {
    return (unsigned)__half_as_ushort(__float2half_rn(v));
}
__device__ __forceinline__ unsigned h_hi(float v, float& rem) {
    __half h = __float2half_rn(v);
    rem = v - __half2float(h);
    return (unsigned)__half_as_ushort(h);
}
__device__ __forceinline__ float fast_tanh(float x) {
    x = fminf(10.f, fmaxf(-10.f, x));
    float u = __expf(2.f * x);
    return __fdividef(u - 1.f, u + 1.f);
}
__device__ __forceinline__ unsigned fenc(float f) {
    unsigned u = __float_as_uint(f);
    return (u & 0x80000000u) ? ~u : (u | 0x80000000u);
}
__device__ __forceinline__ float fdec(unsigned e) {
    unsigned u = (e & 0x80000000u) ? (e & 0x7fffffffu) : ~e;
    return __uint_as_float(u);
}

__global__ __launch_bounds__(256)
void init_rmax(unsigned* __restrict__ r, int n)
{
    int i = blockIdx.x * 256 + threadIdx.x;
    if (i < n) r[i] = 0u;
}

__global__ __launch_bounds__(256)
void pack_pair(const float* __restrict__ X, unsigned* __restrict__ hi,
               unsigned* __restrict__ lo, size_t npairs)
{
    size_t i = (size_t)blockIdx.x * 256 + threadIdx.x;
    if (i >= npairs) return;
    float2 v = reinterpret_cast<const float2*>(X)[i];
    float ra, rb;
    unsigned ha = h_hi(v.x, ra);
    unsigned hb = h_hi(v.y, rb);
    hi[i] = ha | (hb << 16);
    lo[i] = h_bits(ra) | (h_bits(rb) << 16);
}

__global__ __launch_bounds__(256)
void pack_hi_only(const float* __restrict__ X, unsigned* __restrict__ hi, size_t npairs)
{
    size_t i = (size_t)blockIdx.x * 256 + threadIdx.x;
    if (i >= npairs) return;
    float2 v = reinterpret_cast<const float2*>(X)[i];
    hi[i] = h_bits(v.x) | (h_bits(v.y) << 16);
}

__global__ __launch_bounds__(256)
void pack_c(const float* __restrict__ X, unsigned* __restrict__ hi,
            unsigned* __restrict__ lo, float* __restrict__ cnq, int dpairs)
{
    __shared__ float red[256];
    const int row = blockIdx.x;
    const float2* src = reinterpret_cast<const float2*>(X) + (size_t)row * dpairs;
    float s = 0.f;
    for (int i = threadIdx.x; i < dpairs; i += 256) {
        float2 v = src[i];
        float ra, rb;
        unsigned ha = h_hi(v.x, ra);
        unsigned hb = h_hi(v.y, rb);
        size_t o = (size_t)row * dpairs + i;
        hi[o] = ha | (hb << 16);
        lo[o] = h_bits(ra) | (h_bits(rb) << 16);
        s = fmaf(v.x, v.x, s); s = fmaf(v.y, v.y, s);
    }
    red[threadIdx.x] = s; __syncthreads();
    for (int st = 128; st > 0; st >>= 1) {
        if (threadIdx.x < st) red[threadIdx.x] += red[threadIdx.x + st];
        __syncthreads();
    }
    if (threadIdx.x == 0) cnq[row] = 0.25f * red[0];
}

// Single-pass fused exp + transpose + fp16 split pack + row expsum.
// Processes rows [r0base + blockIdx.x*32, +32). R = TOTAL rows (for GT stride).
__global__ __launch_bounds__(256)
void softmax_transpose(const float* __restrict__ G, const unsigned* __restrict__ rmax,
                       unsigned* __restrict__ hi, unsigned* __restrict__ lo,
                       float* __restrict__ sinv, int R, int C, int r0base)
{
    __shared__ float smx[32];
    __shared__ float tile[32][65];
    __shared__ float ssum[32][17];
    const int tid = threadIdx.x;
    const int r0 = r0base + blockIdx.x * 32;
    if (tid < 32) smx[tid] = fdec(rmax[r0 + tid]);
    __syncthreads();

    const int p = tid & 15, q = tid >> 4;
    const float m0 = smx[2 * p], m1 = smx[2 * p + 1];
    float s0 = 0.f, s1 = 0.f;
    const size_t Rh = (size_t)(R >> 1);
    const float* gbase = G + (size_t)r0 * C;

    for (int c0 = 0; c0 < C; c0 += 64) {
        const int cw = (C - c0 >= 64) ? 64 : (C - c0);
        const int csh = (cw == 64) ? 6 : 5;
        for (int i = tid; i < 32 * cw; i += 256) {
            int r = i >> csh, cl = i & (cw - 1);
            tile[r][cl] = gbase[(size_t)r * C + c0 + cl];
        }
        __syncthreads();
        for (int i = tid; i < cw * 16; i += 256) {
            int c = i >> 4;
            float ea = __expf(tile[2 * p][c] - m0);
            float eb = __expf(tile[2 * p + 1][c] - m1);
            s0 += ea; s1 += eb;
            float ra, rb;
            unsigned ha = h_hi(ea, ra);
            unsigned hb = h_hi(eb, rb);
            size_t o = (size_t)(c0 + c) * Rh + (r0 >> 1) + p;
            hi[o] = ha | (hb << 16);
            lo[o] = h_bits(ra) | (h_bits(rb) << 16);
        }
        __syncthreads();
    }

    ssum[2 * p][q] = s0;
    ssum[2 * p + 1][q] = s1;
    __syncthreads();
    if (tid < 32) {
        float s = 0.f;
#pragma unroll
        for (int j = 0; j < 16; j++) s += ssum[tid][j];
        sinv[r0 + tid] = 1.f / s;
    }
}

// scale tT pairs by sinv over pair-column range [mpoff, mpoff+chunkMh)
__global__ __launch_bounds__(256)
void scale_tT(unsigned* __restrict__ tT, const float* __restrict__ sinv,
              int Mh, int mpoff, int chunkMh)
{
    int i = blockIdx.x * 256 + threadIdx.x;
    if (i >= chunkMh) return;
    int mp = mpoff + i;
    int n = blockIdx.y;
    size_t o = (size_t)n * Mh + mp;
    unsigned v = tT[o];
    __half2 h2 = *reinterpret_cast<__half2*>(&v);
    float lo = __half2float(__low2half(h2)) * sinv[2 * mp];
    float hi = __half2float(__high2half(h2)) * sinv[2 * mp + 1];
    tT[o] = h_bits(lo) | (h_bits(hi) << 16);
}

// sum S split-K slices; write fp32 out and optionally h pairs
__global__ __launch_bounds__(256)
void addS_pack(const float* __restrict__ P, float* __restrict__ out,
               unsigned* __restrict__ hi, unsigned* __restrict__ lo,
               size_t n4, size_t str4, int S)
{
    size_t i = (size_t)blockIdx.x * 256 + threadIdx.x;
    if (i >= n4) return;
    const float4* p4 = reinterpret_cast<const float4*>(P);
    float4 a = p4[i];
    for (int s = 1; s < S; s++) {
        float4 b = p4[i + (size_t)s * str4];
        a.x += b.x; a.y += b.y; a.z += b.z; a.w += b.w;
    }
    reinterpret_cast<float4*>(out)[i] = a;
    if (hi) {
        float r0, r1, r2, r3;
        unsigned h0 = h_hi(a.x, r0), h1 = h_hi(a.y, r1);
        unsigned h2 = h_hi(a.z, r2), h3 = h_hi(a.w, r3);
        hi[2 * i]     = h0 | (h1 << 16);
        hi[2 * i + 1] = h2 | (h3 << 16);
        lo[2 * i]     = h_bits(r0) | (h_bits(r1) << 16);
        lo[2 * i + 1] = h_bits(r2) | (h_bits(r3) << 16);
    }
}

// ---------------------------------------------------------------------------
// split fp16 tensor GEMM.  NMMA=3: (A2)x(B2) hh+hl+lh, 3-stage.
// NMMA=2: (A2)x(B1) hh+lh, 4-stage.  NMMA=1: (A1)x(B1) hh, 4-stage.
// yoff: row-block offset (row chunking).  EPI 0: fp32 store.
// EPI 1: tanh(acc+aux[col]) -> transposed fp16 pairs Tt (unnormalized).
// EPI 2: 0.5*acc - aux[col] + per-row atomicMax into rmax.
// ---------------------------------------------------------------------------
#define BK 32
#define KPT 16
#define TILE_B 8192
#define SM_BYTES 98304

__device__ __forceinline__ void mma_f16(float* c, const unsigned* a, const unsigned* b)
{
    asm volatile(
        "mma.sync.aligned.m16n8k16.row.col.f32.f16.f16.f32 "
        "{%0,%1,%2,%3}, {%4,%5,%6,%7}, {%8,%9}, {%0,%1,%2,%3};"
        : "+f"(c[0]), "+f"(c[1]), "+f"(c[2]), "+f"(c[3])
        : "r"(a[0]), "r"(a[1]), "r"(a[2]), "r"(a[3]), "r"(b[0]), "r"(b[1]));
}
__device__ __forceinline__ void ldmx4(unsigned* r, unsigned a)
{
    asm volatile("ldmatrix.sync.aligned.m8n8.x4.shared.b16 {%0,%1,%2,%3}, [%4];"
                 : "=r"(r[0]), "=r"(r[1]), "=r"(r[2]), "=r"(r[3]) : "r"(a));
}
__device__ __forceinline__ void cpa16(unsigned dst, const void* src, bool pred)
{
    int sz = pred ? 16 : 0;
    asm volatile("cp.async.cg.shared.global [%0], [%1], 16, %2;\n"
                 :: "r"(dst), "l"(src), "r"(sz));
}

template <int NMMA, int EPI>
__global__ __launch_bounds__(256, 2)
void gemm8(const unsigned* __restrict__ Ahi, const unsigned* __restrict__ Alo,
           const unsigned* __restrict__ Bhi, const unsigned* __restrict__ Blo,
           const float* __restrict__ aux, float* __restrict__ C,
           unsigned* __restrict__ Tt, unsigned* __restrict__ rmax,
           int M, int N, int K, int ldA, int ldB, int koff,
           int kqPairs, size_t sliceElems, int yoff)
{
    extern __shared__ __align__(16) unsigned char smem[];
    constexpr int NBUF = (NMMA == 3) ? 4 : (NMMA == 2 ? 3 : 2);
    constexpr int NSTG = (NMMA == 3) ? 3 : 4;
    constexpr int PF   = NSTG - 1;
    constexpr int IB   = (NMMA >= 2) ? 2 : 1;
    const int tid  = threadIdx.x;
    const int bm   = (blockIdx.y + yoff) * 128, bn = blockIdx.x * 128;
    const int lane = tid & 31, wid = tid >> 5;
    const int wr   = (wid >> 2) * 64, wc = (wid & 3) * 32;
    const int g    = lane >> 2, t = lane & 3;
    const int kp0base = koff + blockIdx.z * kqPairs;
    float* Cz = C + (size_t)blockIdx.z * sliceElems;

    float acc[4][4][4];
#pragma unroll
    for (int mi = 0; mi < 4; mi++)
#pragma unroll
        for (int ni = 0; ni < 4; ni++)
#pragma unroll
            for (int k = 0; k < 4; k++) acc[mi][ni][k] = 0.f;

    const int NIT = K / BK;
    const unsigned sbase = (unsigned)__cvta_generic_to_shared(smem);
    const unsigned rl = (unsigned)(lane & 15), jsel = (unsigned)(lane >> 4);
    const unsigned X = (rl >> 1) & 3;
    const unsigned moff0 = rl * 64 + (((0 + jsel) ^ X) << 4);
    const unsigned moff1 = rl * 64 + (((2 + jsel) ^ X) << 4);

    auto soff_of = [&](int c) {
        unsigned row = (unsigned)(c >> 2), j = (unsigned)(c & 3);
        return row * 64 + ((j ^ ((row >> 1) & 3)) << 4);
    };
    const unsigned so0 = soff_of(tid), so1 = soff_of(tid + 256);

    auto prefetch = [&](int it) {
        const int s = it % NSTG;
        const int kp0 = kp0base + it * KPT;
        const unsigned stg = sbase + (unsigned)(s * NBUF) * TILE_B;
#pragma unroll
        for (int h = 0; h < 2; h++) {
            int c = tid + h * 256;
            int row = c >> 2, seg = (c & 3) << 2;
            unsigned soff = h ? so1 : so0;
            bool pa = (bm + row) < M;
            bool pb = (bn + row) < N;
            size_t ga = (size_t)(pa ? bm + row : 0) * ldA + kp0 + seg;
            size_t gb = (size_t)(pb ? bn + row : 0) * ldB + kp0 + seg;
            cpa16(stg + 0 * TILE_B + soff, Ahi + ga, pa);
            if (NMMA >= 2) cpa16(stg + 1 * TILE_B + soff, Alo + ga, pa);
            cpa16(stg + IB * TILE_B + soff, Bhi + gb, pb);
            if (NMMA == 3) cpa16(stg + 3 * TILE_B + soff, Blo + gb, pb);
        }
        asm volatile("cp.async.commit_group;\n");
    };

#pragma unroll
    for (int i = 0; i < PF; i++)
        if (i < NIT) prefetch(i);

    for (int it = 0; it < NIT; ++it) {
        const int s = it % NSTG;
        {
            int lvl = NIT - 1 - it;
            if (lvl > NSTG - 2) lvl = NSTG - 2;
            if (lvl >= 2)      asm volatile("cp.async.wait_group 2;\n");
            else if (lvl == 1) asm volatile("cp.async.wait_group 1;\n");
            else               asm volatile("cp.async.wait_group 0;\n");
        }
        __syncthreads();

        const unsigned sA_hi = sbase + (unsigned)(s * NBUF + 0) * TILE_B;
        const unsigned sA_lo = sbase + (unsigned)(s * NBUF + 1) * TILE_B;
        const unsigned sB_hi = sbase + (unsigned)(s * NBUF + IB) * TILE_B;
        const unsigned sB_lo = sbase + (unsigned)(s * NBUF + 3) * TILE_B;

        // ---- half-step ks = 0 ----
        {
            unsigned ah[4][4], al[4][4], bh[4][2], bl[4][2];
#pragma unroll
            for (int mi = 0; mi < 4; mi++) {
                unsigned off = moff0 + (unsigned)((wr + mi * 16) * 64);
                ldmx4(ah[mi], sA_hi + off);
                if (NMMA >= 2) ldmx4(al[mi], sA_lo + off);
            }
#pragma unroll
            for (int nj = 0; nj < 2; nj++) {
                unsigned off = moff0 + (unsigned)((wc + nj * 16) * 64);
                unsigned bt[4];
                ldmx4(bt, sB_hi + off);
                bh[2 * nj][0] = bt[0]; bh[2 * nj + 1][0] = bt[1];
                bh[2 * nj][1] = bt[2]; bh[2 * nj + 1][1] = bt[3];
                if (NMMA == 3) {
                    ldmx4(bt, sB_lo + off);
                    bl[2 * nj][0] = bt[0]; bl[2 * nj + 1][0] = bt[1];
                    bl[2 * nj][1] = bt[2]; bl[2 * nj + 1][1] = bt[3];
                }
            }
#pragma unroll
            for (int mi = 0; mi < 4; mi++)
#pragma unroll
                for (int ni = 0; ni < 4; ni++) {
                    mma_f16(acc[mi][ni], ah[mi], bh[ni]);
                    if (NMMA == 3) mma_f16(acc[mi][ni], ah[mi], bl[ni]);
                    if (NMMA >= 2) mma_f16(acc[mi][ni], al[mi], bh[ni]);
                }
        }

        if (it + PF < NIT) prefetch(it + PF);

        // ---- half-step ks = 1 ----
        {
            unsigned ah[4][4], al[4][4], bh[4][2], bl[4][2];
#pragma unroll
            for (int mi = 0; mi < 4; mi++) {
                unsigned off = moff1 + (unsigned)((wr + mi * 16) * 64);
                ldmx4(ah[mi], sA_hi + off);
                if (NMMA >= 2) ldmx4(al[mi], sA_lo + off);
            }
#pragma unroll
            for (int nj = 0; nj < 2; nj++) {
                unsigned off = moff1 + (unsigned)((wc + nj * 16) * 64);
                unsigned bt[4];
                ldmx4(bt, sB_hi + off);
                bh[2 * nj][0] = bt[0]; bh[2 * nj + 1][0] = bt[1];
                bh[2 * nj][1] = bt[2]; bh[2 * nj + 1][1] = bt[3];
                if (NMMA == 3) {
                    ldmx4(bt, sB_lo + off);
                    bl[2 * nj][0] = bt[0]; bl[2 * nj + 1][0] = bt[1];
                    bl[2 * nj][1] = bt[2]; bl[2 * nj + 1][1] = bt[3];
                }
            }
#pragma unroll
            for (int mi = 0; mi < 4; mi++)
#pragma unroll
                for (int ni = 0; ni < 4; ni++) {
                    mma_f16(acc[mi][ni], ah[mi], bh[ni]);
                    if (NMMA == 3) mma_f16(acc[mi][ni], ah[mi], bl[ni]);
                    if (NMMA >= 2) mma_f16(acc[mi][ni], al[mi], bh[ni]);
                }
        }
    }

    if (EPI == 0 || EPI == 2) {
#pragma unroll
        for (int mi = 0; mi < 4; mi++) {
            int r = bm + wr + mi * 16 + g;
            float m0 = -1e30f, m1 = -1e30f;
#pragma unroll
            for (int ni = 0; ni < 4; ni++) {
                int cc = bn + wc + ni * 8 + 2 * t;
                if (cc < N) {
                    float2 v0, v1;
                    if (EPI == 2) {
                        float a0 = aux[cc], a1 = aux[cc + 1];
                        v0 = make_float2(0.5f * acc[mi][ni][0] - a0,
                                         0.5f * acc[mi][ni][1] - a1);
                        v1 = make_float2(0.5f * acc[mi][ni][2] - a0,
                                         0.5f * acc[mi][ni][3] - a1);
                        m0 = fmaxf(m0, fmaxf(v0.x, v0.y));
                        m1 = fmaxf(m1, fmaxf(v1.x, v1.y));
                    } else {
                        v0 = make_float2(acc[mi][ni][0], acc[mi][ni][1]);
                        v1 = make_float2(acc[mi][ni][2], acc[mi][ni][3]);
                    }
                    if (r < M)
                        *reinterpret_cast<float2*>(&Cz[(size_t)r * N + cc]) = v0;
                    if (r + 8 < M)
                        *reinterpret_cast<float2*>(&Cz[(size_t)(r + 8) * N + cc]) = v1;
                }
            }
            if (EPI == 2) {
                m0 = fmaxf(m0, __shfl_xor_sync(0xffffffffu, m0, 1));
                m0 = fmaxf(m0, __shfl_xor_sync(0xffffffffu, m0, 2));
                m1 = fmaxf(m1, __shfl_xor_sync(0xffffffffu, m1, 1));
                m1 = fmaxf(m1, __shfl_xor_sync(0xffffffffu, m1, 2));
                if (t == 0) {
                    if (r < M)     atomicMax(&rmax[r], fenc(m0));
                    if (r + 8 < M) atomicMax(&rmax[r + 8], fenc(m1));
                }
            }
        }
    } else {
        const size_t Mh = (size_t)(M >> 1);
#pragma unroll
        for (int mi = 0; mi < 4; mi++) {
            int mglob = bm + wr + mi * 16 + g;
#pragma unroll
            for (int ni = 0; ni < 4; ni++) {
                int cc = bn + wc + ni * 8 + 2 * t;
                float b0 = aux[cc], b1 = aux[cc + 1];
                float v[4];
                v[0] = fast_tanh(acc[mi][ni][0] + b0);
                v[1] = fast_tanh(acc[mi][ni][1] + b1);
                v[2] = fast_tanh(acc[mi][ni][2] + b0);
                v[3] = fast_tanh(acc[mi][ni][3] + b1);
#pragma unroll
                for (int vi = 0; vi < 4; vi++) {
                    unsigned hb = h_bits(v[vi]);
                    unsigned oth = __shfl_xor_sync(0xffffffffu, hb, 4);
                    if ((lane & 4) == 0) {
                        int n = cc + (vi & 1);
                        int mp = ((mglob + ((vi >> 1) << 3)) >> 1);
                        Tt[(size_t)n * Mh + mp] = hb | (oth << 16);
                    }
                }
            }
        }
    }
}

// ---------------------------------------------------------------------------
// Host orchestration
// ---------------------------------------------------------------------------
static void run_level(const float* h_fp32, bool need_pack_h,
                      unsigned* hPhi, unsigned* hPlo,
                      int n_prev, int n_cur,
                      unsigned* cPhi, unsigned* cPlo, unsigned* wPhi,
                      const float* b,
                      float* G, float* cnq, unsigned* rmax, float* sinv,
                      unsigned* GThi, unsigned* GTlo, unsigned* tT,
                      float* out, unsigned* outPhi, unsigned* outPlo,
                      cudaStream_t s2, cudaStream_t s3,
                      cudaEvent_t evF, cudaEvent_t evJ,
                      cudaEvent_t* evL, cudaEvent_t evS)
{
    const int ldD = D / 2;
    if (need_pack_h) {
        size_t np = (size_t)n_prev * (D / 2);
        pack_pair<<<(unsigned)((np + 255) / 256), 256>>>(h_fp32, hPhi, hPlo, np);
    }
    init_rmax<<<(n_prev + 255) / 256, 256>>>(rmax, n_prev);
    cudaEventRecord(evF, 0);

    // t = tanh(h@W^T + b) unnormalized (2-term)  [s2]
    cudaStreamWaitEvent(s2, evF, 0);
    {
        dim3 grid(D / 128, n_prev / 128, 1);
        gemm8<2, 1><<<grid, 256, SM_BYTES, s2>>>(hPhi, hPlo, wPhi, nullptr, b,
                                                 nullptr, tT, nullptr,
                                                 n_prev, D, D, ldD, ldD, 0, 0, 0, 0);
    }
    cudaEventRecord(evJ, s2);

    // logits (3-term) in row chunks [null]; softmax+scale chunks [s3]
    const int nch = (n_prev >= 8192) ? 4 : 1;
    const int chRows = n_prev / nch;
    const int Mh = n_prev / 2;
    for (int k = 0; k < nch; k++) {
        dim3 grid((n_cur + 127) / 128, chRows / 128, 1);
        gemm8<3, 2><<<grid, 256, SM_BYTES>>>(hPhi, hPlo, cPhi, cPlo, cnq, G,
                                             nullptr, rmax,
                                             n_prev, n_cur, D, ldD, ldD, 0, 0, 0,
                                             k * (chRows / 128));
        cudaEventRecord(evL[k], 0);
        cudaStreamWaitEvent(s3, evL[k], 0);
        softmax_transpose<<<chRows / 32, 256, 0, s3>>>(G, rmax, GThi, GTlo, sinv,
                                                       n_prev, n_cur, k * chRows);
        if (k == 0) cudaStreamWaitEvent(s3, evJ, 0);   // need t before scaling
        {
            const int chMh = chRows / 2;
            dim3 sgrid((chMh + 255) / 256, D);
            scale_tT<<<sgrid, 256, 0, s3>>>(tT, sinv, Mh, k * chMh, chMh);
        }
    }
    cudaEventRecord(evS, s3);
    cudaStreamWaitEvent(0, evS, 0);

    // out = e_hi^T @ t'_hi  (1-term), split-K via gridDim.z  [null]
    {
        const int S = (n_prev >= 2048) ? 8 : 1;
        const int ldK = n_prev / 2;
        const int Ks = n_prev / S;
        dim3 grid(D / 128, (n_cur + 127) / 128, S);
        if (S > 1) {
            gemm8<1, 0><<<grid, 256, SM_BYTES>>>(GThi, nullptr, tT, nullptr, nullptr,
                                                 G, nullptr, nullptr,
                                                 n_cur, D, Ks, ldK, ldK, 0,
                                                 Ks / 2, (size_t)n_cur * D, 0);
            size_t n4 = (size_t)n_cur * D / 4;
            addS_pack<<<(unsigned)((n4 + 255) / 256), 256>>>(G, out, outPhi, outPlo,
                                                             n4, n4, S);
        } else {
            gemm8<1, 0><<<grid, 256, SM_BYTES>>>(GThi, nullptr, tT, nullptr, nullptr,
                                                 out, nullptr, nullptr,
                                                 n_cur, D, n_prev, ldK, ldK, 0,
                                                 0, 0, 0);
        }
    }
}

extern "C" void kernel_launch(void* const* d_in, const int* in_sizes, int n_in,
                              void* d_out, int out_size)
{
    const float* h0 = (const float*)d_in[0];
    const float* c1 = (const float*)d_in[1];
    const float* c2 = (const float*)d_in[2];
    const float* c3 = (const float*)d_in[3];
    const float* W1 = (const float*)d_in[4];
    const float* b1 = (const float*)d_in[5];
    const float* W2 = (const float*)d_in[6];
    const float* b2 = (const float*)d_in[7];
    const float* W3 = (const float*)d_in[8];
    const float* b3 = (const float*)d_in[9];
    float* out = (float*)d_out;

    static cudaStream_t s2 = nullptr, s3 = nullptr;
    static cudaEvent_t evF[3], evJ[3], evS[3], evL[3][4], evPre, evStart;
    if (!s2) {
        cudaStreamCreateWithFlags(&s2, cudaStreamNonBlocking);
        cudaStreamCreateWithFlags(&s3, cudaStreamNonBlocking);
        for (int i = 0; i < 3; i++) {
            cudaEventCreateWithFlags(&evF[i], cudaEventDisableTiming);
            cudaEventCreateWithFlags(&evJ[i], cudaEventDisableTiming);
            cudaEventCreateWithFlags(&evS[i], cudaEventDisableTiming);
            for (int k = 0; k < 4; k++)
                cudaEventCreateWithFlags(&evL[i][k], cudaEventDisableTiming);
        }
        cudaEventCreateWithFlags(&evPre, cudaEventDisableTiming);
        cudaEventCreateWithFlags(&evStart, cudaEventDisableTiming);
    }

    cudaFuncSetAttribute(gemm8<3, 2>, cudaFuncAttributeMaxDynamicSharedMemorySize, SM_BYTES);
    cudaFuncSetAttribute(gemm8<2, 1>, cudaFuncAttributeMaxDynamicSharedMemorySize, SM_BYTES);
    cudaFuncSetAttribute(gemm8<1, 0>, cudaFuncAttributeMaxDynamicSharedMemorySize, SM_BYTES);

    float *pG, *pHn, *psinv, *pcnq1, *pcnq2, *pcnq3;
    unsigned *hPhi, *hPlo, *GThi, *GTlo, *tT, *prmax;
    unsigned *cPhi1, *cPlo1, *cPhi2, *cPlo2, *cPhi3, *cPlo3;
    unsigned *wPhi1, *wPhi2, *wPhi3;
    cudaGetSymbolAddress((void**)&pG,    g_G);
    cudaGetSymbolAddress((void**)&pHn,   g_Hn);
    cudaGetSymbolAddress((void**)&psinv, g_sinv);
    cudaGetSymbolAddress((void**)&prmax, g_rmax);
    cudaGetSymbolAddress((void**)&hPhi,  g_hPhi);
    cudaGetSymbolAddress((void**)&hPlo,  g_hPlo);
    cudaGetSymbolAddress((void**)&GThi,  g_GThi);
    cudaGetSymbolAddress((void**)&GTlo,  g_GTlo);
    cudaGetSymbolAddress((void**)&tT,    g_tT);
    cudaGetSymbolAddress((void**)&pcnq1, g_cnq1);
    cudaGetSymbolAddress((void**)&pcnq2, g_cnq2);
    cudaGetSymbolAddress((void**)&pcnq3, g_cnq3);
    cudaGetSymbolAddress((void**)&cPhi1, g_cPhi1);
    cudaGetSymbolAddress((void**)&cPlo1, g_cPlo1);
    cudaGetSymbolAddress((void**)&cPhi2, g_cPhi2);
    cudaGetSymbolAddress((void**)&cPlo2, g_cPlo2);
    cudaGetSymbolAddress((void**)&cPhi3, g_cPhi3);
    cudaGetSymbolAddress((void**)&cPlo3, g_cPlo3);
    cudaGetSymbolAddress((void**)&wPhi1, g_wPhi1);
    cudaGetSymbolAddress((void**)&wPhi2, g_wPhi2);
    cudaGetSymbolAddress((void**)&wPhi3, g_wPhi3);

    const size_t npW = (size_t)D * (D / 2);
    const unsigned gW = (unsigned)((npW + 255) / 256);

    // Bring s2 and s3 into the capture graph BEFORE their first launches.
    cudaEventRecord(evStart, 0);
    cudaStreamWaitEvent(s2, evStart, 0);
    cudaStreamWaitEvent(s3, evStart, 0);

    // prepack level-2/3 c and W on s2 (independent of level 1)
    pack_c<<<N2, 256, 0, s2>>>(c2, cPhi2, cPlo2, pcnq2, D / 2);
    pack_hi_only<<<gW, 256, 0, s2>>>(W2, wPhi2, npW);
    pack_c<<<N3, 256, 0, s2>>>(c3, cPhi3, cPlo3, pcnq3, D / 2);
    pack_hi_only<<<gW, 256, 0, s2>>>(W3, wPhi3, npW);
    cudaEventRecord(evPre, s2);

    // level-1 c and W on null stream (needed before level-1 logits/t)
    pack_c<<<N1, 256>>>(c1, cPhi1, cPlo1, pcnq1, D / 2);
    pack_hi_only<<<gW, 256>>>(W1, wPhi1, npW);

    run_level(h0, true, hPhi, hPlo, N0, N1, cPhi1, cPlo1, wPhi1, b1,
              pG, pcnq1, prmax, psinv, GThi, GTlo, tT,
              pHn, hPhi, hPlo, s2, s3, evF[0], evJ[0], evL[0], evS[0]);
    cudaStreamWaitEvent(0, evPre, 0);
    run_level(pHn, false, hPhi, hPlo, N1, N2, cPhi2, cPlo2, wPhi2, b2,
              pG, pcnq2, prmax, psinv, GThi, GTlo, tT,
              pHn, hPhi, hPlo, s2, s3, evF[1], evJ[1], evL[1], evS[1]);
    run_level(pHn, false, hPhi, hPlo, N2, N3, cPhi3, cPlo3, wPhi3, b3,
              pG, pcnq3, prmax, psinv, GThi, GTlo, tT,
              out, nullptr, nullptr, s2, s3, evF[2], evJ[2], evL[2], evS[2]);
}

// round 16
// speedup vs baseline: 1.0900x; 1.0900x over previous
#include <cuda_runtime.h>
#include <cuda_fp16.h>
#include <math.h>

// ---------------------------------------------------------------------------
// HierarchicalClustering via split-fp16 tensor-core GEMMs (mma.sync HMMA).
//   logits = 0.5*(h @ c^T) - 0.25*||c||^2   (||h||^2 cancels in softmax)
//   p      = softmax_rows(logits)
//   t      = tanh(h @ W^T + b)
//   h_next = p^T @ t = (e^{l-m})^T @ (t * sinv)
// fp16 pair-packed u32 operands [rows][K/2].
//   logits: (h_hi,h_lo)x(c_hi,c_lo) 3 MMAs (single launch, never chunked)
//   t     : (h_hi,h_lo)x(W_hi)      2 MMAs  (fork stream s2)
//   out   : e_hi x t_hi             1 MMA   (K-chunked partials on s2,
//                                            overlapping softmax chunks)
// GEMM: 128x128 CTA tile, 8 warps of 64x32, 2 CTAs/SM, XOR-swizzled 64B smem
// rows, one __syncthreads per k-iter, mid-iteration prefetch.
// ---------------------------------------------------------------------------

#define D 1024
#define N0 16384
#define N1 2048
#define N2 256
#define N3 32

__device__ float    g_G[(size_t)N0 * N1];
__device__ float    g_Hn[(size_t)N1 * D];
__device__ unsigned g_hPhi[(size_t)N0 * (D / 2)];
__device__ unsigned g_hPlo[(size_t)N0 * (D / 2)];
__device__ unsigned g_cPhi1[(size_t)N1 * (D / 2)];
__device__ unsigned g_cPlo1[(size_t)N1 * (D / 2)];
__device__ unsigned g_cPhi2[(size_t)N2 * (D / 2)];
__device__ unsigned g_cPlo2[(size_t)N2 * (D / 2)];
__device__ unsigned g_cPhi3[(size_t)N3 * (D / 2)];
__device__ unsigned g_cPlo3[(size_t)N3 * (D / 2)];
__device__ unsigned g_wPhi1[(size_t)D * (D / 2)];
__device__ unsigned g_wPhi2[(size_t)D * (D / 2)];
__device__ unsigned g_wPhi3[(size_t)D * (D / 2)];
__device__ unsigned g_GThi[(size_t)N1 * (N0 / 2)];
__device__ unsigned g_GTlo[(size_t)N1 * (N0 / 2)];
__device__ unsigned g_tT[(size_t)D * (N0 / 2)];
__device__ float    g_cnq1[N1];
__device__ float    g_cnq2[N2];
__device__ float    g_cnq3[N3];
__device__ unsigned g_rmax[N0];
__device__ float    g_sinv[N0];

// ------------------------------- helpers -----------------------------------
__device__ __forceinline__ unsigned h_bits(float v) {
    return (unsigned)__half_as_ushort(__float2half_rn(v));
}
__device__ __forceinline__ unsigned h_hi(float v, float& rem) {
    __half h = __float2half_rn(v);
    rem = v - __half2float(h);
    return (unsigned)__half_as_ushort(h);
}
__device__ __forceinline__ float fast_tanh(float x) {
    x = fminf(10.f, fmaxf(-10.f, x));
    float u = __expf(2.f * x);
    return __fdividef(u - 1.f, u + 1.f);
}
__device__ __forceinline__ unsigned fenc(float f) {
    unsigned u = __float_as_uint(f);
    return (u & 0x80000000u) ? ~u : (u | 0x80000000u);
}
__device__ __forceinline__ float fdec(unsigned e) {
    unsigned u = (e & 0x80000000u) ? (e & 0x7fffffffu) : ~e;
    return __uint_as_float(u);
}

__global__ __launch_bounds__(256)
void init_rmax(unsigned* __restrict__ r, int n)
{
    int i = blockIdx.x * 256 + threadIdx.x;
    if (i < n) r[i] = 0u;
}

__global__ __launch_bounds__(256)
void pack_pair(const float* __restrict__ X, unsigned* __restrict__ hi,
               unsigned* __restrict__ lo, size_t npairs)
{
    size_t i = (size_t)blockIdx.x * 256 + threadIdx.x;
    if (i >= npairs) return;
    float2 v = reinterpret_cast<const float2*>(X)[i];
    float ra, rb;
    unsigned ha = h_hi(v.x, ra);
    unsigned hb = h_hi(v.y, rb);
    hi[i] = ha | (hb << 16);
    lo[i] = h_bits(ra) | (h_bits(rb) << 16);
}

__global__ __launch_bounds__(256)
void pack_hi_only(const float* __restrict__ X, unsigned* __restrict__ hi, size_t npairs)
{
    size_t i = (size_t)blockIdx.x * 256 + threadIdx.x;
    if (i >= npairs) return;
    float2 v = reinterpret_cast<const float2*>(X)[i];
    hi[i] = h_bits(v.x) | (h_bits(v.y) << 16);
}

__global__ __launch_bounds__(256)
void pack_c(const float* __restrict__ X, unsigned* __restrict__ hi,
            unsigned* __restrict__ lo, float* __restrict__ cnq, int dpairs)
{
    __shared__ float red[256];
    const int row = blockIdx.x;
    const float2* src = reinterpret_cast<const float2*>(X) + (size_t)row * dpairs;
    float s = 0.f;
    for (int i = threadIdx.x; i < dpairs; i += 256) {
        float2 v = src[i];
        float ra, rb;
        unsigned ha = h_hi(v.x, ra);
        unsigned hb = h_hi(v.y, rb);
        size_t o = (size_t)row * dpairs + i;
        hi[o] = ha | (hb << 16);
        lo[o] = h_bits(ra) | (h_bits(rb) << 16);
        s = fmaf(v.x, v.x, s); s = fmaf(v.y, v.y, s);
    }
    red[threadIdx.x] = s; __syncthreads();
    for (int st = 128; st > 0; st >>= 1) {
        if (threadIdx.x < st) red[threadIdx.x] += red[threadIdx.x + st];
        __syncthreads();
    }
    if (threadIdx.x == 0) cnq[row] = 0.25f * red[0];
}

// Single-pass fused exp + transpose + fp16 split pack + row expsum.
// Processes rows [r0base + blockIdx.x*32, +32). R = total rows (GT stride).
__global__ __launch_bounds__(256)
void softmax_transpose(const float* __restrict__ G, const unsigned* __restrict__ rmax,
                       unsigned* __restrict__ hi, unsigned* __restrict__ lo,
                       float* __restrict__ sinv, int R, int C, int r0base)
{
    __shared__ float smx[32];
    __shared__ float tile[32][65];
    __shared__ float ssum[32][17];
    const int tid = threadIdx.x;
    const int r0 = r0base + blockIdx.x * 32;
    if (tid < 32) smx[tid] = fdec(rmax[r0 + tid]);
    __syncthreads();

    const int p = tid & 15, q = tid >> 4;
    const float m0 = smx[2 * p], m1 = smx[2 * p + 1];
    float s0 = 0.f, s1 = 0.f;
    const size_t Rh = (size_t)(R >> 1);
    const float* gbase = G + (size_t)r0 * C;

    for (int c0 = 0; c0 < C; c0 += 64) {
        const int cw = (C - c0 >= 64) ? 64 : (C - c0);
        const int csh = (cw == 64) ? 6 : 5;
        for (int i = tid; i < 32 * cw; i += 256) {
            int r = i >> csh, cl = i & (cw - 1);
            tile[r][cl] = gbase[(size_t)r * C + c0 + cl];
        }
        __syncthreads();
        for (int i = tid; i < cw * 16; i += 256) {
            int c = i >> 4;
            float ea = __expf(tile[2 * p][c] - m0);
            float eb = __expf(tile[2 * p + 1][c] - m1);
            s0 += ea; s1 += eb;
            float ra, rb;
            unsigned ha = h_hi(ea, ra);
            unsigned hb = h_hi(eb, rb);
            size_t o = (size_t)(c0 + c) * Rh + (r0 >> 1) + p;
            hi[o] = ha | (hb << 16);
            lo[o] = h_bits(ra) | (h_bits(rb) << 16);
        }
        __syncthreads();
    }

    ssum[2 * p][q] = s0;
    ssum[2 * p + 1][q] = s1;
    __syncthreads();
    if (tid < 32) {
        float s = 0.f;
#pragma unroll
        for (int j = 0; j < 16; j++) s += ssum[tid][j];
        sinv[r0 + tid] = 1.f / s;
    }
}

// scale tT pairs by sinv over pair-column range [mpoff, mpoff+chunkMh)
__global__ __launch_bounds__(256)
void scale_tT(unsigned* __restrict__ tT, const float* __restrict__ sinv,
              int Mh, int mpoff, int chunkMh)
{
    int i = blockIdx.x * 256 + threadIdx.x;
    if (i >= chunkMh) return;
    int mp = mpoff + i;
    int n = blockIdx.y;
    size_t o = (size_t)n * Mh + mp;
    unsigned v = tT[o];
    __half2 h2 = *reinterpret_cast<__half2*>(&v);
    float lo = __half2float(__low2half(h2)) * sinv[2 * mp];
    float hi = __half2float(__high2half(h2)) * sinv[2 * mp + 1];
    tT[o] = h_bits(lo) | (h_bits(hi) << 16);
}

// sum S split-K slices; write fp32 out and optionally h pairs
__global__ __launch_bounds__(256)
void addS_pack(const float* __restrict__ P, float* __restrict__ out,
               unsigned* __restrict__ hi, unsigned* __restrict__ lo,
               size_t n4, size_t str4, int S)
{
    size_t i = (size_t)blockIdx.x * 256 + threadIdx.x;
    if (i >= n4) return;
    const float4* p4 = reinterpret_cast<const float4*>(P);
    float4 a = p4[i];
    for (int s = 1; s < S; s++) {
        float4 b = p4[i + (size_t)s * str4];
        a.x += b.x; a.y += b.y; a.z += b.z; a.w += b.w;
    }
    reinterpret_cast<float4*>(out)[i] = a;
    if (hi) {
        float r0, r1, r2, r3;
        unsigned h0 = h_hi(a.x, r0), h1 = h_hi(a.y, r1);
        unsigned h2 = h_hi(a.z, r2), h3 = h_hi(a.w, r3);
        hi[2 * i]     = h0 | (h1 << 16);
        hi[2 * i + 1] = h2 | (h3 << 16);
        lo[2 * i]     = h_bits(r0) | (h_bits(r1) << 16);
        lo[2 * i + 1] = h_bits(r2) | (h_bits(r3) << 16);
    }
}

// ---------------------------------------------------------------------------
// split fp16 tensor GEMM.  NMMA=3: (A2)x(B2) hh+hl+lh, 3-stage.
// NMMA=2: (A2)x(B1) hh+lh, 4-stage.  NMMA=1: (A1)x(B1) hh, 4-stage.
// EPI 0: fp32 store.  EPI 1: tanh(acc+aux[col]) -> transposed fp16 pairs Tt
// (unnormalized; scale_tT applies sinv).  EPI 2: 0.5*acc - aux[col] + rmax.
// ---------------------------------------------------------------------------
#define BK 32
#define KPT 16
#define TILE_B 8192
#define SM_BYTES 98304

__device__ __forceinline__ void mma_f16(float* c, const unsigned* a, const unsigned* b)
{
    asm volatile(
        "mma.sync.aligned.m16n8k16.row.col.f32.f16.f16.f32 "
        "{%0,%1,%2,%3}, {%4,%5,%6,%7}, {%8,%9}, {%0,%1,%2,%3};"
        : "+f"(c[0]), "+f"(c[1]), "+f"(c[2]), "+f"(c[3])
        : "r"(a[0]), "r"(a[1]), "r"(a[2]), "r"(a[3]), "r"(b[0]), "r"(b[1]));
}
__device__ __forceinline__ void ldmx4(unsigned* r, unsigned a)
{
    asm volatile("ldmatrix.sync.aligned.m8n8.x4.shared.b16 {%0,%1,%2,%3}, [%4];"
                 : "=r"(r[0]), "=r"(r[1]), "=r"(r[2]), "=r"(r[3]) : "r"(a));
}
__device__ __forceinline__ void cpa16(unsigned dst, const void* src, bool pred)
{
    int sz = pred ? 16 : 0;
    asm volatile("cp.async.cg.shared.global [%0], [%1], 16, %2;\n"
                 :: "r"(dst), "l"(src), "r"(sz));
}

template <int NMMA, int EPI>
__global__ __launch_bounds__(256, 2)
void gemm8(const unsigned* __restrict__ Ahi, const unsigned* __restrict__ Alo,
           const unsigned* __restrict__ Bhi, const unsigned* __restrict__ Blo,
           const float* __restrict__ aux, float* __restrict__ C,
           unsigned* __restrict__ Tt, unsigned* __restrict__ rmax,
           int M, int N, int K, int ldA, int ldB, int koff,
           int kqPairs, size_t sliceElems)
{
    extern __shared__ __align__(16) unsigned char smem[];
    constexpr int NBUF = (NMMA == 3) ? 4 : (NMMA == 2 ? 3 : 2);
    constexpr int NSTG = (NMMA == 3) ? 3 : 4;
    constexpr int PF   = NSTG - 1;
    constexpr int IB   = (NMMA >= 2) ? 2 : 1;
    const int tid  = threadIdx.x;
    const int bm   = blockIdx.y * 128, bn = blockIdx.x * 128;
    const int lane = tid & 31, wid = tid >> 5;
    const int wr   = (wid >> 2) * 64, wc = (wid & 3) * 32;
    const int g    = lane >> 2, t = lane & 3;
    const int kp0base = koff + blockIdx.z * kqPairs;
    float* Cz = C + (size_t)blockIdx.z * sliceElems;

    float acc[4][4][4];
#pragma unroll
    for (int mi = 0; mi < 4; mi++)
#pragma unroll
        for (int ni = 0; ni < 4; ni++)
#pragma unroll
            for (int k = 0; k < 4; k++) acc[mi][ni][k] = 0.f;

    const int NIT = K / BK;
    const unsigned sbase = (unsigned)__cvta_generic_to_shared(smem);
    const unsigned rl = (unsigned)(lane & 15), jsel = (unsigned)(lane >> 4);
    const unsigned X = (rl >> 1) & 3;
    const unsigned moff0 = rl * 64 + (((0 + jsel) ^ X) << 4);
    const unsigned moff1 = rl * 64 + (((2 + jsel) ^ X) << 4);

    auto soff_of = [&](int c) {
        unsigned row = (unsigned)(c >> 2), j = (unsigned)(c & 3);
        return row * 64 + ((j ^ ((row >> 1) & 3)) << 4);
    };
    const unsigned so0 = soff_of(tid), so1 = soff_of(tid + 256);

    auto prefetch = [&](int it) {
        const int s = it % NSTG;
        const int kp0 = kp0base + it * KPT;
        const unsigned stg = sbase + (unsigned)(s * NBUF) * TILE_B;
#pragma unroll
        for (int h = 0; h < 2; h++) {
            int c = tid + h * 256;
            int row = c >> 2, seg = (c & 3) << 2;
            unsigned soff = h ? so1 : so0;
            bool pa = (bm + row) < M;
            bool pb = (bn + row) < N;
            size_t ga = (size_t)(pa ? bm + row : 0) * ldA + kp0 + seg;
            size_t gb = (size_t)(pb ? bn + row : 0) * ldB + kp0 + seg;
            cpa16(stg + 0 * TILE_B + soff, Ahi + ga, pa);
            if (NMMA >= 2) cpa16(stg + 1 * TILE_B + soff, Alo + ga, pa);
            cpa16(stg + IB * TILE_B + soff, Bhi + gb, pb);
            if (NMMA == 3) cpa16(stg + 3 * TILE_B + soff, Blo + gb, pb);
        }
        asm volatile("cp.async.commit_group;\n");
    };

#pragma unroll
    for (int i = 0; i < PF; i++)
        if (i < NIT) prefetch(i);

    for (int it = 0; it < NIT; ++it) {
        const int s = it % NSTG;
        {
            int lvl = NIT - 1 - it;
            if (lvl > NSTG - 2) lvl = NSTG - 2;
            if (lvl >= 2)      asm volatile("cp.async.wait_group 2;\n");
            else if (lvl == 1) asm volatile("cp.async.wait_group 1;\n");
            else               asm volatile("cp.async.wait_group 0;\n");
        }
        __syncthreads();

        const unsigned sA_hi = sbase + (unsigned)(s * NBUF + 0) * TILE_B;
        const unsigned sA_lo = sbase + (unsigned)(s * NBUF + 1) * TILE_B;
        const unsigned sB_hi = sbase + (unsigned)(s * NBUF + IB) * TILE_B;
        const unsigned sB_lo = sbase + (unsigned)(s * NBUF + 3) * TILE_B;

        // ---- half-step ks = 0 ----
        {
            unsigned ah[4][4], al[4][4], bh[4][2], bl[4][2];
#pragma unroll
            for (int mi = 0; mi < 4; mi++) {
                unsigned off = moff0 + (unsigned)((wr + mi * 16) * 64);
                ldmx4(ah[mi], sA_hi + off);
                if (NMMA >= 2) ldmx4(al[mi], sA_lo + off);
            }
#pragma unroll
            for (int nj = 0; nj < 2; nj++) {
                unsigned off = moff0 + (unsigned)((wc + nj * 16) * 64);
                unsigned bt[4];
                ldmx4(bt, sB_hi + off);
                bh[2 * nj][0] = bt[0]; bh[2 * nj + 1][0] = bt[1];
                bh[2 * nj][1] = bt[2]; bh[2 * nj + 1][1] = bt[3];
                if (NMMA == 3) {
                    ldmx4(bt, sB_lo + off);
                    bl[2 * nj][0] = bt[0]; bl[2 * nj + 1][0] = bt[1];
                    bl[2 * nj][1] = bt[2]; bl[2 * nj + 1][1] = bt[3];
                }
            }
#pragma unroll
            for (int mi = 0; mi < 4; mi++)
#pragma unroll
                for (int ni = 0; ni < 4; ni++) {
                    mma_f16(acc[mi][ni], ah[mi], bh[ni]);
                    if (NMMA == 3) mma_f16(acc[mi][ni], ah[mi], bl[ni]);
                    if (NMMA >= 2) mma_f16(acc[mi][ni], al[mi], bh[ni]);
                }
        }

        if (it + PF < NIT) prefetch(it + PF);

        // ---- half-step ks = 1 ----
        {
            unsigned ah[4][4], al[4][4], bh[4][2], bl[4][2];
#pragma unroll
            for (int mi = 0; mi < 4; mi++) {
                unsigned off = moff1 + (unsigned)((wr + mi * 16) * 64);
                ldmx4(ah[mi], sA_hi + off);
                if (NMMA >= 2) ldmx4(al[mi], sA_lo + off);
            }
#pragma unroll
            for (int nj = 0; nj < 2; nj++) {
                unsigned off = moff1 + (unsigned)((wc + nj * 16) * 64);
                unsigned bt[4];
                ldmx4(bt, sB_hi + off);
                bh[2 * nj][0] = bt[0]; bh[2 * nj + 1][0] = bt[1];
                bh[2 * nj][1] = bt[2]; bh[2 * nj + 1][1] = bt[3];
                if (NMMA == 3) {
                    ldmx4(bt, sB_lo + off);
                    bl[2 * nj][0] = bt[0]; bl[2 * nj + 1][0] = bt[1];
                    bl[2 * nj][1] = bt[2]; bl[2 * nj + 1][1] = bt[3];
                }
            }
#pragma unroll
            for (int mi = 0; mi < 4; mi++)
#pragma unroll
                for (int ni = 0; ni < 4; ni++) {
                    mma_f16(acc[mi][ni], ah[mi], bh[ni]);
                    if (NMMA == 3) mma_f16(acc[mi][ni], ah[mi], bl[ni]);
                    if (NMMA >= 2) mma_f16(acc[mi][ni], al[mi], bh[ni]);
                }
        }
    }

    if (EPI == 0 || EPI == 2) {
#pragma unroll
        for (int mi = 0; mi < 4; mi++) {
            int r = bm + wr + mi * 16 + g;
            float m0 = -1e30f, m1 = -1e30f;
#pragma unroll
            for (int ni = 0; ni < 4; ni++) {
                int cc = bn + wc + ni * 8 + 2 * t;
                if (cc < N) {
                    float2 v0, v1;
                    if (EPI == 2) {
                        float a0 = aux[cc], a1 = aux[cc + 1];
                        v0 = make_float2(0.5f * acc[mi][ni][0] - a0,
                                         0.5f * acc[mi][ni][1] - a1);
                        v1 = make_float2(0.5f * acc[mi][ni][2] - a0,
                                         0.5f * acc[mi][ni][3] - a1);
                        m0 = fmaxf(m0, fmaxf(v0.x, v0.y));
                        m1 = fmaxf(m1, fmaxf(v1.x, v1.y));
                    } else {
                        v0 = make_float2(acc[mi][ni][0], acc[mi][ni][1]);
                        v1 = make_float2(acc[mi][ni][2], acc[mi][ni][3]);
                    }
                    if (r < M)
                        *reinterpret_cast<float2*>(&Cz[(size_t)r * N + cc]) = v0;
                    if (r + 8 < M)
                        *reinterpret_cast<float2*>(&Cz[(size_t)(r + 8) * N + cc]) = v1;
                }
            }
            if (EPI == 2) {
                m0 = fmaxf(m0, __shfl_xor_sync(0xffffffffu, m0, 1));
                m0 = fmaxf(m0, __shfl_xor_sync(0xffffffffu, m0, 2));
                m1 = fmaxf(m1, __shfl_xor_sync(0xffffffffu, m1, 1));
                m1 = fmaxf(m1, __shfl_xor_sync(0xffffffffu, m1, 2));
                if (t == 0) {
                    if (r < M)     atomicMax(&rmax[r], fenc(m0));
                    if (r + 8 < M) atomicMax(&rmax[r + 8], fenc(m1));
                }
            }
        }
    } else {
        const size_t Mh = (size_t)(M >> 1);
#pragma unroll
        for (int mi = 0; mi < 4; mi++) {
            int mglob = bm + wr + mi * 16 + g;
#pragma unroll
            for (int ni = 0; ni < 4; ni++) {
                int cc = bn + wc + ni * 8 + 2 * t;
                float b0 = aux[cc], b1 = aux[cc + 1];
                float v[4];
                v[0] = fast_tanh(acc[mi][ni][0] + b0);
                v[1] = fast_tanh(acc[mi][ni][1] + b1);
                v[2] = fast_tanh(acc[mi][ni][2] + b0);
                v[3] = fast_tanh(acc[mi][ni][3] + b1);
#pragma unroll
                for (int vi = 0; vi < 4; vi++) {
                    unsigned hb = h_bits(v[vi]);
                    unsigned oth = __shfl_xor_sync(0xffffffffu, hb, 4);
                    if ((lane & 4) == 0) {
                        int n = cc + (vi & 1);
                        int mp = ((mglob + ((vi >> 1) << 3)) >> 1);
                        Tt[(size_t)n * Mh + mp] = hb | (oth << 16);
                    }
                }
            }
        }
    }
}

// ---------------------------------------------------------------------------
// Host orchestration
// ---------------------------------------------------------------------------
static void run_level(const float* h_fp32, bool need_pack_h,
                      unsigned* hPhi, unsigned* hPlo,
                      int n_prev, int n_cur,
                      unsigned* cPhi, unsigned* cPlo, unsigned* wPhi,
                      const float* b,
                      float* G, float* cnq, unsigned* rmax, float* sinv,
                      unsigned* GThi, unsigned* GTlo, unsigned* tT,
                      float* out, unsigned* outPhi, unsigned* outPlo,
                      cudaStream_t s2, cudaEvent_t evF,
                      cudaEvent_t* evC, cudaEvent_t evO)
{
    const int ldD = D / 2;
    if (need_pack_h) {
        size_t np = (size_t)n_prev * (D / 2);
        pack_pair<<<(unsigned)((np + 255) / 256), 256>>>(h_fp32, hPhi, hPlo, np);
    }
    init_rmax<<<(n_prev + 255) / 256, 256>>>(rmax, n_prev);
    cudaEventRecord(evF, 0);

    // t = tanh(h@W^T + b) unnormalized (2-term)  [s2]
    cudaStreamWaitEvent(s2, evF, 0);
    {
        dim3 grid(D / 128, n_prev / 128, 1);
        gemm8<2, 1><<<grid, 256, SM_BYTES, s2>>>(hPhi, hPlo, wPhi, nullptr, b,
                                                 nullptr, tT, nullptr,
                                                 n_prev, D, D, ldD, ldD, 0, 0, 0);
    }

    // logits (3-term), ONE launch  [null]
    {
        dim3 grid((n_cur + 127) / 128, n_prev / 128, 1);
        gemm8<3, 2><<<grid, 256, SM_BYTES>>>(hPhi, hPlo, cPhi, cPlo, cnq, G,
                                             nullptr, rmax,
                                             n_prev, n_cur, D, ldD, ldD, 0, 0, 0);
    }

    // softmax row-chunks [null]; scale + out K-partials [s2], overlapped
    const int nch = (n_prev >= 8192) ? 2 : 1;
    const int chRows = n_prev / nch;
    const int Mh = n_prev / 2;
    const int ldK = n_prev / 2;
    const int Schunk = (n_prev >= 2048) ? (8 / nch) : 1;
    for (int k = 0; k < nch; k++) {
        softmax_transpose<<<chRows / 32, 256>>>(G, rmax, GThi, GTlo, sinv,
                                                n_prev, n_cur, k * chRows);
        cudaEventRecord(evC[k], 0);
        cudaStreamWaitEvent(s2, evC[k], 0);
        const int chMh = chRows / 2;
        {
            dim3 sgrid((chMh + 255) / 256, D);
            scale_tT<<<sgrid, 256, 0, s2>>>(tT, sinv, Mh, k * chMh, chMh);
        }
        if (Schunk > 1) {
            const int Ks = chRows / Schunk;
            dim3 grid(D / 128, (n_cur + 127) / 128, Schunk);
            gemm8<1, 0><<<grid, 256, SM_BYTES, s2>>>(
                GThi, nullptr, tT, nullptr, nullptr,
                G + (size_t)k * Schunk * n_cur * D, nullptr, nullptr,
                n_cur, D, Ks, ldK, ldK, k * chMh, Ks / 2, (size_t)n_cur * D);
        } else {
            dim3 grid(D / 128, (n_cur + 127) / 128, 1);
            gemm8<1, 0><<<grid, 256, SM_BYTES, s2>>>(
                GThi, nullptr, tT, nullptr, nullptr, out, nullptr, nullptr,
                n_cur, D, n_prev, ldK, ldK, 0, 0, 0);
        }
    }
    cudaEventRecord(evO, s2);
    cudaStreamWaitEvent(0, evO, 0);
    if (Schunk * nch > 1) {
        size_t n4 = (size_t)n_cur * D / 4;
        addS_pack<<<(unsigned)((n4 + 255) / 256), 256>>>(G, out, outPhi, outPlo,
                                                         n4, n4, Schunk * nch);
    }
}

extern "C" void kernel_launch(void* const* d_in, const int* in_sizes, int n_in,
                              void* d_out, int out_size)
{
    const float* h0 = (const float*)d_in[0];
    const float* c1 = (const float*)d_in[1];
    const float* c2 = (const float*)d_in[2];
    const float* c3 = (const float*)d_in[3];
    const float* W1 = (const float*)d_in[4];
    const float* b1 = (const float*)d_in[5];
    const float* W2 = (const float*)d_in[6];
    const float* b2 = (const float*)d_in[7];
    const float* W3 = (const float*)d_in[8];
    const float* b3 = (const float*)d_in[9];
    float* out = (float*)d_out;

    static cudaStream_t s2 = nullptr;
    static cudaEvent_t evF[3], evO[3], evC[3][2], evPre, evStart;
    if (!s2) {
        cudaStreamCreateWithFlags(&s2, cudaStreamNonBlocking);
        for (int i = 0; i < 3; i++) {
            cudaEventCreateWithFlags(&evF[i], cudaEventDisableTiming);
            cudaEventCreateWithFlags(&evO[i], cudaEventDisableTiming);
            for (int k = 0; k < 2; k++)
                cudaEventCreateWithFlags(&evC[i][k], cudaEventDisableTiming);
        }
        cudaEventCreateWithFlags(&evPre, cudaEventDisableTiming);
        cudaEventCreateWithFlags(&evStart, cudaEventDisableTiming);
    }

    cudaFuncSetAttribute(gemm8<3, 2>, cudaFuncAttributeMaxDynamicSharedMemorySize, SM_BYTES);
    cudaFuncSetAttribute(gemm8<2, 1>, cudaFuncAttributeMaxDynamicSharedMemorySize, SM_BYTES);
    cudaFuncSetAttribute(gemm8<1, 0>, cudaFuncAttributeMaxDynamicSharedMemorySize, SM_BYTES);

    float *pG, *pHn, *psinv, *pcnq1, *pcnq2, *pcnq3;
    unsigned *hPhi, *hPlo, *GThi, *GTlo, *tT, *prmax;
    unsigned *cPhi1, *cPlo1, *cPhi2, *cPlo2, *cPhi3, *cPlo3;
    unsigned *wPhi1, *wPhi2, *wPhi3;
    cudaGetSymbolAddress((void**)&pG,    g_G);
    cudaGetSymbolAddress((void**)&pHn,   g_Hn);
    cudaGetSymbolAddress((void**)&psinv, g_sinv);
    cudaGetSymbolAddress((void**)&prmax, g_rmax);
    cudaGetSymbolAddress((void**)&hPhi,  g_hPhi);
    cudaGetSymbolAddress((void**)&hPlo,  g_hPlo);
    cudaGetSymbolAddress((void**)&GThi,  g_GThi);
    cudaGetSymbolAddress((void**)&GTlo,  g_GTlo);
    cudaGetSymbolAddress((void**)&tT,    g_tT);
    cudaGetSymbolAddress((void**)&pcnq1, g_cnq1);
    cudaGetSymbolAddress((void**)&pcnq2, g_cnq2);
    cudaGetSymbolAddress((void**)&pcnq3, g_cnq3);
    cudaGetSymbolAddress((void**)&cPhi1, g_cPhi1);
    cudaGetSymbolAddress((void**)&cPlo1, g_cPlo1);
    cudaGetSymbolAddress((void**)&cPhi2, g_cPhi2);
    cudaGetSymbolAddress((void**)&cPlo2, g_cPlo2);
    cudaGetSymbolAddress((void**)&cPhi3, g_cPhi3);
    cudaGetSymbolAddress((void**)&cPlo3, g_cPlo3);
    cudaGetSymbolAddress((void**)&wPhi1, g_wPhi1);
    cudaGetSymbolAddress((void**)&wPhi2, g_wPhi2);
    cudaGetSymbolAddress((void**)&wPhi3, g_wPhi3);

    const size_t npW = (size_t)D * (D / 2);
    const unsigned gW = (unsigned)((npW + 255) / 256);

    // Bring s2 into the capture graph BEFORE its first launch.
    cudaEventRecord(evStart, 0);
    cudaStreamWaitEvent(s2, evStart, 0);

    // prepack level-2/3 c and W on s2 (independent of level 1)
    pack_c<<<N2, 256, 0, s2>>>(c2, cPhi2, cPlo2, pcnq2, D / 2);
    pack_hi_only<<<gW, 256, 0, s2>>>(W2, wPhi2, npW);
    pack_c<<<N3, 256, 0, s2>>>(c3, cPhi3, cPlo3, pcnq3, D / 2);
    pack_hi_only<<<gW, 256, 0, s2>>>(W3, wPhi3, npW);
    cudaEventRecord(evPre, s2);

    // level-1 c and W on null stream (needed before level-1 logits/t)
    pack_c<<<N1, 256>>>(c1, cPhi1, cPlo1, pcnq1, D / 2);
    pack_hi_only<<<gW, 256>>>(W1, wPhi1, npW);

    run_level(h0, true, hPhi, hPlo, N0, N1, cPhi1, cPlo1, wPhi1, b1,
              pG, pcnq1, prmax, psinv, GThi, GTlo, tT,
              pHn, hPhi, hPlo, s2, evF[0], evC[0], evO[0]);
    cudaStreamWaitEvent(0, evPre, 0);
    run_level(pHn, false, hPhi, hPlo, N1, N2, cPhi2, cPlo2, wPhi2, b2,
              pG, pcnq2, prmax, psinv, GThi, GTlo, tT,
              pHn, hPhi, hPlo, s2, evF[1], evC[1], evO[1]);
    run_level(pHn, false, hPhi, hPlo, N2, N3, cPhi3, cPlo3, wPhi3, b3,
              pG, pcnq3, prmax, psinv, GThi, GTlo, tT,
              out, nullptr, nullptr, s2, evF[2], evC[2], evO[2]);
}

// round 17
// speedup vs baseline: 1.1475x; 1.0527x over previous
#include <cuda_runtime.h>
#include <cuda_fp16.h>
#include <math.h>

// ---------------------------------------------------------------------------
// HierarchicalClustering via split-fp16 tensor-core GEMMs (mma.sync HMMA).
//   logits = 0.5*(h @ c^T) - 0.25*||c||^2   (||h||^2 cancels in softmax)
//   p      = softmax_rows(logits)
//   t      = tanh(h @ W^T + b)
//   h_next = p^T @ t = (e^{l-m})^T @ (t * sinv)
// fp16 pair-packed u32 operands [rows][K/2].
//   logits: (h_hi,h_lo)x(c_hi,c_lo) 3 MMAs
//   t     : (h_hi,h_lo)x(W_hi)      2 MMAs  (fork stream s2, hidden)
//   out   : e_hi x t_hi             1 MMA   (GT lo never materialized)
// GEMM: 128x128 CTA tile, 8 warps of 64x32, 2 CTAs/SM, XOR-swizzled 64B smem
// rows, one __syncthreads per k-iter, mid-iteration prefetch.
// Serial phase schedule (r15/r16 proved overlap against softmax/out loses).
// ---------------------------------------------------------------------------

#define D 1024
#define N0 16384
#define N1 2048
#define N2 256
#define N3 32

__device__ float    g_G[(size_t)N0 * N1];
__device__ float    g_Hn[(size_t)N1 * D];
__device__ unsigned g_hPhi[(size_t)N0 * (D / 2)];
__device__ unsigned g_hPlo[(size_t)N0 * (D / 2)];
__device__ unsigned g_cPhi1[(size_t)N1 * (D / 2)];
__device__ unsigned g_cPlo1[(size_t)N1 * (D / 2)];
__device__ unsigned g_cPhi2[(size_t)N2 * (D / 2)];
__device__ unsigned g_cPlo2[(size_t)N2 * (D / 2)];
__device__ unsigned g_cPhi3[(size_t)N3 * (D / 2)];
__device__ unsigned g_cPlo3[(size_t)N3 * (D / 2)];
__device__ unsigned g_wPhi1[(size_t)D * (D / 2)];
__device__ unsigned g_wPhi2[(size_t)D * (D / 2)];
__device__ unsigned g_wPhi3[(size_t)D * (D / 2)];
__device__ unsigned g_GThi[(size_t)N1 * (N0 / 2)];
__device__ unsigned g_tT[(size_t)D * (N0 / 2)];
__device__ float    g_cnq1[N1];
__device__ float    g_cnq2[N2];
__device__ float    g_cnq3[N3];
__device__ unsigned g_rmax[N0];
__device__ float    g_sinv[N0];

// ------------------------------- helpers -----------------------------------
__device__ __forceinline__ unsigned h_bits(float v) {
    return (unsigned)__half_as_ushort(__float2half_rn(v));
}
__device__ __forceinline__ unsigned h_hi(float v, float& rem) {
    __half h = __float2half_rn(v);
    rem = v - __half2float(h);
    return (unsigned)__half_as_ushort(h);
}
__device__ __forceinline__ float fast_tanh(float x) {
    x = fminf(10.f, fmaxf(-10.f, x));
    float u = __expf(2.f * x);
    return __fdividef(u - 1.f, u + 1.f);
}
__device__ __forceinline__ unsigned fenc(float f) {
    unsigned u = __float_as_uint(f);
    return (u & 0x80000000u) ? ~u : (u | 0x80000000u);
}
__device__ __forceinline__ float fdec(unsigned e) {
    unsigned u = (e & 0x80000000u) ? (e & 0x7fffffffu) : ~e;
    return __uint_as_float(u);
}

__global__ __launch_bounds__(256)
void init_rmax(unsigned* __restrict__ r, int n)
{
    int i = blockIdx.x * 256 + threadIdx.x;
    if (i < n) r[i] = 0u;
}

__global__ __launch_bounds__(256)
void pack_pair(const float* __restrict__ X, unsigned* __restrict__ hi,
               unsigned* __restrict__ lo, size_t npairs)
{
    size_t i = (size_t)blockIdx.x * 256 + threadIdx.x;
    if (i >= npairs) return;
    float2 v = reinterpret_cast<const float2*>(X)[i];
    float ra, rb;
    unsigned ha = h_hi(v.x, ra);
    unsigned hb = h_hi(v.y, rb);
    hi[i] = ha | (hb << 16);
    lo[i] = h_bits(ra) | (h_bits(rb) << 16);
}

__global__ __launch_bounds__(256)
void pack_hi_only(const float* __restrict__ X, unsigned* __restrict__ hi, size_t npairs)
{
    size_t i = (size_t)blockIdx.x * 256 + threadIdx.x;
    if (i >= npairs) return;
    float2 v = reinterpret_cast<const float2*>(X)[i];
    hi[i] = h_bits(v.x) | (h_bits(v.y) << 16);
}

__global__ __launch_bounds__(256)
void pack_c(const float* __restrict__ X, unsigned* __restrict__ hi,
            unsigned* __restrict__ lo, float* __restrict__ cnq, int dpairs)
{
    __shared__ float red[256];
    const int row = blockIdx.x;
    const float2* src = reinterpret_cast<const float2*>(X) + (size_t)row * dpairs;
    float s = 0.f;
    for (int i = threadIdx.x; i < dpairs; i += 256) {
        float2 v = src[i];
        float ra, rb;
        unsigned ha = h_hi(v.x, ra);
        unsigned hb = h_hi(v.y, rb);
        size_t o = (size_t)row * dpairs + i;
        hi[o] = ha | (hb << 16);
        lo[o] = h_bits(ra) | (h_bits(rb) << 16);
        s = fmaf(v.x, v.x, s); s = fmaf(v.y, v.y, s);
    }
    red[threadIdx.x] = s; __syncthreads();
    for (int st = 128; st > 0; st >>= 1) {
        if (threadIdx.x < st) red[threadIdx.x] += red[threadIdx.x + st];
        __syncthreads();
    }
    if (threadIdx.x == 0) cnq[row] = 0.25f * red[0];
}

// Single-pass fused exp + transpose + fp16 pack (hi only) + row expsum.
__global__ __launch_bounds__(256)
void softmax_transpose(const float* __restrict__ G, const unsigned* __restrict__ rmax,
                       unsigned* __restrict__ hi, float* __restrict__ sinv,
                       int R, int C)
{
    __shared__ float smx[32];
    __shared__ float tile[32][65];
    __shared__ float ssum[32][17];
    const int tid = threadIdx.x;
    const int r0 = blockIdx.x * 32;
    if (tid < 32) smx[tid] = fdec(rmax[r0 + tid]);
    __syncthreads();

    const int p = tid & 15, q = tid >> 4;
    const float m0 = smx[2 * p], m1 = smx[2 * p + 1];
    float s0 = 0.f, s1 = 0.f;
    const size_t Rh = (size_t)(R >> 1);
    const float* gbase = G + (size_t)r0 * C;

    for (int c0 = 0; c0 < C; c0 += 64) {
        const int cw = (C - c0 >= 64) ? 64 : (C - c0);
        const int csh = (cw == 64) ? 6 : 5;
        for (int i = tid; i < 32 * cw; i += 256) {
            int r = i >> csh, cl = i & (cw - 1);
            tile[r][cl] = gbase[(size_t)r * C + c0 + cl];
        }
        __syncthreads();
        for (int i = tid; i < cw * 16; i += 256) {
            int c = i >> 4;
            float ea = __expf(tile[2 * p][c] - m0);
            float eb = __expf(tile[2 * p + 1][c] - m1);
            s0 += ea; s1 += eb;
            size_t o = (size_t)(c0 + c) * Rh + (r0 >> 1) + p;
            hi[o] = h_bits(ea) | (h_bits(eb) << 16);
        }
        __syncthreads();
    }

    ssum[2 * p][q] = s0;
    ssum[2 * p + 1][q] = s1;
    __syncthreads();
    if (tid < 32) {
        float s = 0.f;
#pragma unroll
        for (int j = 0; j < 16; j++) s += ssum[tid][j];
        sinv[r0 + tid] = 1.f / s;
    }
}

// scale tT pairs by sinv: pair mp holds rows {2mp, 2mp+1}
__global__ __launch_bounds__(256)
void scale_tT(unsigned* __restrict__ tT, const float* __restrict__ sinv, int Mh)
{
    int mp = blockIdx.x * 256 + threadIdx.x;
    if (mp >= Mh) return;
    int n = blockIdx.y;
    size_t o = (size_t)n * Mh + mp;
    unsigned v = tT[o];
    __half2 h2 = *reinterpret_cast<__half2*>(&v);
    float lo = __half2float(__low2half(h2)) * sinv[2 * mp];
    float hi = __half2float(__high2half(h2)) * sinv[2 * mp + 1];
    tT[o] = h_bits(lo) | (h_bits(hi) << 16);
}

// sum S split-K slices; write fp32 out and optionally h pairs
__global__ __launch_bounds__(256)
void addS_pack(const float* __restrict__ P, float* __restrict__ out,
               unsigned* __restrict__ hi, unsigned* __restrict__ lo,
               size_t n4, size_t str4, int S)
{
    size_t i = (size_t)blockIdx.x * 256 + threadIdx.x;
    if (i >= n4) return;
    const float4* p4 = reinterpret_cast<const float4*>(P);
    float4 a = p4[i];
    for (int s = 1; s < S; s++) {
        float4 b = p4[i + (size_t)s * str4];
        a.x += b.x; a.y += b.y; a.z += b.z; a.w += b.w;
    }
    reinterpret_cast<float4*>(out)[i] = a;
    if (hi) {
        float r0, r1, r2, r3;
        unsigned h0 = h_hi(a.x, r0), h1 = h_hi(a.y, r1);
        unsigned h2 = h_hi(a.z, r2), h3 = h_hi(a.w, r3);
        hi[2 * i]     = h0 | (h1 << 16);
        hi[2 * i + 1] = h2 | (h3 << 16);
        lo[2 * i]     = h_bits(r0) | (h_bits(r1) << 16);
        lo[2 * i + 1] = h_bits(r2) | (h_bits(r3) << 16);
    }
}

// ---------------------------------------------------------------------------
// split fp16 tensor GEMM.  NMMA=3: (A2)x(B2) hh+hl+lh, 3-stage.
// NMMA=2: (A2)x(B1) hh+lh, 4-stage.  NMMA=1: (A1)x(B1) hh, 4-stage.
// EPI 0: fp32 store.  EPI 1: tanh(acc+aux[col]) -> transposed fp16 pairs Tt
// (unnormalized; scale_tT applies sinv).  EPI 2: 0.5*acc - aux[col] + rmax.
// ---------------------------------------------------------------------------
#define BK 32
#define KPT 16
#define TILE_B 8192
#define SM_BYTES 98304

__device__ __forceinline__ void mma_f16(float* c, const unsigned* a, const unsigned* b)
{
    asm volatile(
        "mma.sync.aligned.m16n8k16.row.col.f32.f16.f16.f32 "
        "{%0,%1,%2,%3}, {%4,%5,%6,%7}, {%8,%9}, {%0,%1,%2,%3};"
        : "+f"(c[0]), "+f"(c[1]), "+f"(c[2]), "+f"(c[3])
        : "r"(a[0]), "r"(a[1]), "r"(a[2]), "r"(a[3]), "r"(b[0]), "r"(b[1]));
}
__device__ __forceinline__ void ldmx4(unsigned* r, unsigned a)
{
    asm volatile("ldmatrix.sync.aligned.m8n8.x4.shared.b16 {%0,%1,%2,%3}, [%4];"
                 : "=r"(r[0]), "=r"(r[1]), "=r"(r[2]), "=r"(r[3]) : "r"(a));
}
__device__ __forceinline__ void cpa16(unsigned dst, const void* src, bool pred)
{
    int sz = pred ? 16 : 0;
    asm volatile("cp.async.cg.shared.global [%0], [%1], 16, %2;\n"
                 :: "r"(dst), "l"(src), "r"(sz));
}

template <int NMMA, int EPI>
__global__ __launch_bounds__(256, 2)
void gemm8(const unsigned* __restrict__ Ahi, const unsigned* __restrict__ Alo,
           const unsigned* __restrict__ Bhi, const unsigned* __restrict__ Blo,
           const float* __restrict__ aux, float* __restrict__ C,
           unsigned* __restrict__ Tt, unsigned* __restrict__ rmax,
           int M, int N, int K, int ldA, int ldB, int koff,
           int kqPairs, size_t sliceElems)
{
    extern __shared__ __align__(16) unsigned char smem[];
    constexpr int NBUF = (NMMA == 3) ? 4 : (NMMA == 2 ? 3 : 2);
    constexpr int NSTG = (NMMA == 3) ? 3 : 4;
    constexpr int PF   = NSTG - 1;
    constexpr int IB   = (NMMA >= 2) ? 2 : 1;
    const int tid  = threadIdx.x;
    const int bm   = blockIdx.y * 128, bn = blockIdx.x * 128;
    const int lane = tid & 31, wid = tid >> 5;
    const int wr   = (wid >> 2) * 64, wc = (wid & 3) * 32;
    const int g    = lane >> 2, t = lane & 3;
    const int kp0base = koff + blockIdx.z * kqPairs;
    float* Cz = C + (size_t)blockIdx.z * sliceElems;

    float acc[4][4][4];
#pragma unroll
    for (int mi = 0; mi < 4; mi++)
#pragma unroll
        for (int ni = 0; ni < 4; ni++)
#pragma unroll
            for (int k = 0; k < 4; k++) acc[mi][ni][k] = 0.f;

    const int NIT = K / BK;
    const unsigned sbase = (unsigned)__cvta_generic_to_shared(smem);
    const unsigned rl = (unsigned)(lane & 15), jsel = (unsigned)(lane >> 4);
    const unsigned X = (rl >> 1) & 3;
    const unsigned moff0 = rl * 64 + (((0 + jsel) ^ X) << 4);
    const unsigned moff1 = rl * 64 + (((2 + jsel) ^ X) << 4);

    auto soff_of = [&](int c) {
        unsigned row = (unsigned)(c >> 2), j = (unsigned)(c & 3);
        return row * 64 + ((j ^ ((row >> 1) & 3)) << 4);
    };
    const unsigned so0 = soff_of(tid), so1 = soff_of(tid + 256);

    auto prefetch = [&](int it) {
        const int s = it % NSTG;
        const int kp0 = kp0base + it * KPT;
        const unsigned stg = sbase + (unsigned)(s * NBUF) * TILE_B;
#pragma unroll
        for (int h = 0; h < 2; h++) {
            int c = tid + h * 256;
            int row = c >> 2, seg = (c & 3) << 2;
            unsigned soff = h ? so1 : so0;
            bool pa = (bm + row) < M;
            bool pb = (bn + row) < N;
            size_t ga = (size_t)(pa ? bm + row : 0) * ldA + kp0 + seg;
            size_t gb = (size_t)(pb ? bn + row : 0) * ldB + kp0 + seg;
            cpa16(stg + 0 * TILE_B + soff, Ahi + ga, pa);
            if (NMMA >= 2) cpa16(stg + 1 * TILE_B + soff, Alo + ga, pa);
            cpa16(stg + IB * TILE_B + soff, Bhi + gb, pb);
            if (NMMA == 3) cpa16(stg + 3 * TILE_B + soff, Blo + gb, pb);
        }
        asm volatile("cp.async.commit_group;\n");
    };

#pragma unroll
    for (int i = 0; i < PF; i++)
        if (i < NIT) prefetch(i);

    for (int it = 0; it < NIT; ++it) {
        const int s = it % NSTG;
        {
            int lvl = NIT - 1 - it;
            if (lvl > NSTG - 2) lvl = NSTG - 2;
            if (lvl >= 2)      asm volatile("cp.async.wait_group 2;\n");
            else if (lvl == 1) asm volatile("cp.async.wait_group 1;\n");
            else               asm volatile("cp.async.wait_group 0;\n");
        }
        __syncthreads();

        const unsigned sA_hi = sbase + (unsigned)(s * NBUF + 0) * TILE_B;
        const unsigned sA_lo = sbase + (unsigned)(s * NBUF + 1) * TILE_B;
        const unsigned sB_hi = sbase + (unsigned)(s * NBUF + IB) * TILE_B;
        const unsigned sB_lo = sbase + (unsigned)(s * NBUF + 3) * TILE_B;

        // ---- half-step ks = 0 ----
        {
            unsigned ah[4][4], al[4][4], bh[4][2], bl[4][2];
#pragma unroll
            for (int mi = 0; mi < 4; mi++) {
                unsigned off = moff0 + (unsigned)((wr + mi * 16) * 64);
                ldmx4(ah[mi], sA_hi + off);
                if (NMMA >= 2) ldmx4(al[mi], sA_lo + off);
            }
#pragma unroll
            for (int nj = 0; nj < 2; nj++) {
                unsigned off = moff0 + (unsigned)((wc + nj * 16) * 64);
                unsigned bt[4];
                ldmx4(bt, sB_hi + off);
                bh[2 * nj][0] = bt[0]; bh[2 * nj + 1][0] = bt[1];
                bh[2 * nj][1] = bt[2]; bh[2 * nj + 1][1] = bt[3];
                if (NMMA == 3) {
                    ldmx4(bt, sB_lo + off);
                    bl[2 * nj][0] = bt[0]; bl[2 * nj + 1][0] = bt[1];
                    bl[2 * nj][1] = bt[2]; bl[2 * nj + 1][1] = bt[3];
                }
            }
#pragma unroll
            for (int mi = 0; mi < 4; mi++)
#pragma unroll
                for (int ni = 0; ni < 4; ni++) {
                    mma_f16(acc[mi][ni], ah[mi], bh[ni]);
                    if (NMMA == 3) mma_f16(acc[mi][ni], ah[mi], bl[ni]);
                    if (NMMA >= 2) mma_f16(acc[mi][ni], al[mi], bh[ni]);
                }
        }

        if (it + PF < NIT) prefetch(it + PF);

        // ---- half-step ks = 1 ----
        {
            unsigned ah[4][4], al[4][4], bh[4][2], bl[4][2];
#pragma unroll
            for (int mi = 0; mi < 4; mi++) {
                unsigned off = moff1 + (unsigned)((wr + mi * 16) * 64);
                ldmx4(ah[mi], sA_hi + off);
                if (NMMA >= 2) ldmx4(al[mi], sA_lo + off);
            }
#pragma unroll
            for (int nj = 0; nj < 2; nj++) {
                unsigned off = moff1 + (unsigned)((wc + nj * 16) * 64);
                unsigned bt[4];
                ldmx4(bt, sB_hi + off);
                bh[2 * nj][0] = bt[0]; bh[2 * nj + 1][0] = bt[1];
                bh[2 * nj][1] = bt[2]; bh[2 * nj + 1][1] = bt[3];
                if (NMMA == 3) {
                    ldmx4(bt, sB_lo + off);
                    bl[2 * nj][0] = bt[0]; bl[2 * nj + 1][0] = bt[1];
                    bl[2 * nj][1] = bt[2]; bl[2 * nj + 1][1] = bt[3];
                }
            }
#pragma unroll
            for (int mi = 0; mi < 4; mi++)
#pragma unroll
                for (int ni = 0; ni < 4; ni++) {
                    mma_f16(acc[mi][ni], ah[mi], bh[ni]);
                    if (NMMA == 3) mma_f16(acc[mi][ni], ah[mi], bl[ni]);
                    if (NMMA >= 2) mma_f16(acc[mi][ni], al[mi], bh[ni]);
                }
        }
    }

    if (EPI == 0 || EPI == 2) {
#pragma unroll
        for (int mi = 0; mi < 4; mi++) {
            int r = bm + wr + mi * 16 + g;
            float m0 = -1e30f, m1 = -1e30f;
#pragma unroll
            for (int ni = 0; ni < 4; ni++) {
                int cc = bn + wc + ni * 8 + 2 * t;
                if (cc < N) {
                    float2 v0, v1;
                    if (EPI == 2) {
                        float a0 = aux[cc], a1 = aux[cc + 1];
                        v0 = make_float2(0.5f * acc[mi][ni][0] - a0,
                                         0.5f * acc[mi][ni][1] - a1);
                        v1 = make_float2(0.5f * acc[mi][ni][2] - a0,
                                         0.5f * acc[mi][ni][3] - a1);
                        m0 = fmaxf(m0, fmaxf(v0.x, v0.y));
                        m1 = fmaxf(m1, fmaxf(v1.x, v1.y));
                    } else {
                        v0 = make_float2(acc[mi][ni][0], acc[mi][ni][1]);
                        v1 = make_float2(acc[mi][ni][2], acc[mi][ni][3]);
                    }
                    if (r < M)
                        *reinterpret_cast<float2*>(&Cz[(size_t)r * N + cc]) = v0;
                    if (r + 8 < M)
                        *reinterpret_cast<float2*>(&Cz[(size_t)(r + 8) * N + cc]) = v1;
                }
            }
            if (EPI == 2) {
                m0 = fmaxf(m0, __shfl_xor_sync(0xffffffffu, m0, 1));
                m0 = fmaxf(m0, __shfl_xor_sync(0xffffffffu, m0, 2));
                m1 = fmaxf(m1, __shfl_xor_sync(0xffffffffu, m1, 1));
                m1 = fmaxf(m1, __shfl_xor_sync(0xffffffffu, m1, 2));
                if (t == 0) {
                    if (r < M)     atomicMax(&rmax[r], fenc(m0));
                    if (r + 8 < M) atomicMax(&rmax[r + 8], fenc(m1));
                }
            }
        }
    } else {
        const size_t Mh = (size_t)(M >> 1);
#pragma unroll
        for (int mi = 0; mi < 4; mi++) {
            int mglob = bm + wr + mi * 16 + g;
#pragma unroll
            for (int ni = 0; ni < 4; ni++) {
                int cc = bn + wc + ni * 8 + 2 * t;
                float b0 = aux[cc], b1 = aux[cc + 1];
                float v[4];
                v[0] = fast_tanh(acc[mi][ni][0] + b0);
                v[1] = fast_tanh(acc[mi][ni][1] + b1);
                v[2] = fast_tanh(acc[mi][ni][2] + b0);
                v[3] = fast_tanh(acc[mi][ni][3] + b1);
#pragma unroll
                for (int vi = 0; vi < 4; vi++) {
                    unsigned hb = h_bits(v[vi]);
                    unsigned oth = __shfl_xor_sync(0xffffffffu, hb, 4);
                    if ((lane & 4) == 0) {
                        int n = cc + (vi & 1);
                        int mp = ((mglob + ((vi >> 1) << 3)) >> 1);
                        Tt[(size_t)n * Mh + mp] = hb | (oth << 16);
                    }
                }
            }
        }
    }
}

// ---------------------------------------------------------------------------
// Host orchestration (r14 serial schedule)
// ---------------------------------------------------------------------------
static void run_level(const float* h_fp32, bool need_pack_h,
                      unsigned* hPhi, unsigned* hPlo,
                      int n_prev, int n_cur,
                      unsigned* cPhi, unsigned* cPlo, unsigned* wPhi,
                      const float* b,
                      float* G, float* cnq, unsigned* rmax, float* sinv,
                      unsigned* GThi, unsigned* tT,
                      float* out, unsigned* outPhi, unsigned* outPlo,
                      cudaStream_t s2, cudaEvent_t evF, cudaEvent_t evJ)
{
    const int ldD = D / 2;
    if (need_pack_h) {
        size_t np = (size_t)n_prev * (D / 2);
        pack_pair<<<(unsigned)((np + 255) / 256), 256>>>(h_fp32, hPhi, hPlo, np);
    }
    init_rmax<<<(n_prev + 255) / 256, 256>>>(rmax, n_prev);
    cudaEventRecord(evF, 0);

    // logits (3-term) + row-max atomics   [null]
    {
        dim3 grid((n_cur + 127) / 128, n_prev / 128, 1);
        gemm8<3, 2><<<grid, 256, SM_BYTES>>>(hPhi, hPlo, cPhi, cPlo, cnq, G,
                                             nullptr, rmax,
                                             n_prev, n_cur, D, ldD, ldD, 0, 0, 0);
    }
    // t = tanh(h@W^T + b) unnormalized (2-term)  [s2, hidden under logits]
    cudaStreamWaitEvent(s2, evF, 0);
    {
        dim3 grid(D / 128, n_prev / 128, 1);
        gemm8<2, 1><<<grid, 256, SM_BYTES, s2>>>(hPhi, hPlo, wPhi, nullptr, b,
                                                 nullptr, tT, nullptr,
                                                 n_prev, D, D, ldD, ldD, 0, 0, 0);
    }
    cudaEventRecord(evJ, s2);

    // GT(hi only) = exp(l - m), sinv = 1/rowsum  [null]
    softmax_transpose<<<n_prev / 32, 256>>>(G, rmax, GThi, sinv, n_prev, n_cur);
    cudaStreamWaitEvent(0, evJ, 0);
    {
        const int Mh = n_prev / 2;
        dim3 grid((Mh + 255) / 256, D);
        scale_tT<<<grid, 256>>>(tT, sinv, Mh);
    }
    // out = e_hi^T @ t'_hi  (1-term), split-K via gridDim.z
    {
        const int S = (n_prev >= 2048) ? 8 : 1;
        const int ldK = n_prev / 2;
        const int Ks = n_prev / S;
        dim3 grid(D / 128, (n_cur + 127) / 128, S);
        if (S > 1) {
            gemm8<1, 0><<<grid, 256, SM_BYTES>>>(GThi, nullptr, tT, nullptr, nullptr,
                                                 G, nullptr, nullptr,
                                                 n_cur, D, Ks, ldK, ldK, 0,
                                                 Ks / 2, (size_t)n_cur * D);
            size_t n4 = (size_t)n_cur * D / 4;
            addS_pack<<<(unsigned)((n4 + 255) / 256), 256>>>(G, out, outPhi, outPlo,
                                                             n4, n4, S);
        } else {
            gemm8<1, 0><<<grid, 256, SM_BYTES>>>(GThi, nullptr, tT, nullptr, nullptr,
                                                 out, nullptr, nullptr,
                                                 n_cur, D, n_prev, ldK, ldK, 0,
                                                 0, 0);
        }
    }
}

extern "C" void kernel_launch(void* const* d_in, const int* in_sizes, int n_in,
                              void* d_out, int out_size)
{
    const float* h0 = (const float*)d_in[0];
    const float* c1 = (const float*)d_in[1];
    const float* c2 = (const float*)d_in[2];
    const float* c3 = (const float*)d_in[3];
    const float* W1 = (const float*)d_in[4];
    const float* b1 = (const float*)d_in[5];
    const float* W2 = (const float*)d_in[6];
    const float* b2 = (const float*)d_in[7];
    const float* W3 = (const float*)d_in[8];
    const float* b3 = (const float*)d_in[9];
    float* out = (float*)d_out;

    static cudaStream_t s2 = nullptr;
    static cudaEvent_t evF[3], evJ[3], evPre, evStart;
    if (!s2) {
        cudaStreamCreateWithFlags(&s2, cudaStreamNonBlocking);
        for (int i = 0; i < 3; i++) {
            cudaEventCreateWithFlags(&evF[i], cudaEventDisableTiming);
            cudaEventCreateWithFlags(&evJ[i], cudaEventDisableTiming);
        }
        cudaEventCreateWithFlags(&evPre, cudaEventDisableTiming);
        cudaEventCreateWithFlags(&evStart, cudaEventDisableTiming);
    }

    cudaFuncSetAttribute(gemm8<3, 2>, cudaFuncAttributeMaxDynamicSharedMemorySize, SM_BYTES);
    cudaFuncSetAttribute(gemm8<2, 1>, cudaFuncAttributeMaxDynamicSharedMemorySize, SM_BYTES);
    cudaFuncSetAttribute(gemm8<1, 0>, cudaFuncAttributeMaxDynamicSharedMemorySize, SM_BYTES);

    float *pG, *pHn, *psinv, *pcnq1, *pcnq2, *pcnq3;
    unsigned *hPhi, *hPlo, *GThi, *tT, *prmax;
    unsigned *cPhi1, *cPlo1, *cPhi2, *cPlo2, *cPhi3, *cPlo3;
    unsigned *wPhi1, *wPhi2, *wPhi3;
    cudaGetSymbolAddress((void**)&pG,    g_G);
    cudaGetSymbolAddress((void**)&pHn,   g_Hn);
    cudaGetSymbolAddress((void**)&psinv, g_sinv);
    cudaGetSymbolAddress((void**)&prmax, g_rmax);
    cudaGetSymbolAddress((void**)&hPhi,  g_hPhi);
    cudaGetSymbolAddress((void**)&hPlo,  g_hPlo);
    cudaGetSymbolAddress((void**)&GThi,  g_GThi);
    cudaGetSymbolAddress((void**)&tT,    g_tT);
    cudaGetSymbolAddress((void**)&pcnq1, g_cnq1);
    cudaGetSymbolAddress((void**)&pcnq2, g_cnq2);
    cudaGetSymbolAddress((void**)&pcnq3, g_cnq3);
    cudaGetSymbolAddress((void**)&cPhi1, g_cPhi1);
    cudaGetSymbolAddress((void**)&cPlo1, g_cPlo1);
    cudaGetSymbolAddress((void**)&cPhi2, g_cPhi2);
    cudaGetSymbolAddress((void**)&cPlo2, g_cPlo2);
    cudaGetSymbolAddress((void**)&cPhi3, g_cPhi3);
    cudaGetSymbolAddress((void**)&cPlo3, g_cPlo3);
    cudaGetSymbolAddress((void**)&wPhi1, g_wPhi1);
    cudaGetSymbolAddress((void**)&wPhi2, g_wPhi2);
    cudaGetSymbolAddress((void**)&wPhi3, g_wPhi3);

    const size_t npW = (size_t)D * (D / 2);
    const unsigned gW = (unsigned)((npW + 255) / 256);

    // Bring s2 into the capture graph BEFORE its first launch.
    cudaEventRecord(evStart, 0);
    cudaStreamWaitEvent(s2, evStart, 0);

    // prepack level-2/3 c and W on s2 (independent of level 1)
    pack_c<<<N2, 256, 0, s2>>>(c2, cPhi2, cPlo2, pcnq2, D / 2);
    pack_hi_only<<<gW, 256, 0, s2>>>(W2, wPhi2, npW);
    pack_c<<<N3, 256, 0, s2>>>(c3, cPhi3, cPlo3, pcnq3, D / 2);
    pack_hi_only<<<gW, 256, 0, s2>>>(W3, wPhi3, npW);
    cudaEventRecord(evPre, s2);

    // level-1 c and W on null stream (needed before level-1 logits/t)
    pack_c<<<N1, 256>>>(c1, cPhi1, cPlo1, pcnq1, D / 2);
    pack_hi_only<<<gW, 256>>>(W1, wPhi1, npW);

    run_level(h0, true, hPhi, hPlo, N0, N1, cPhi1, cPlo1, wPhi1, b1,
              pG, pcnq1, prmax, psinv, GThi, tT,
              pHn, hPhi, hPlo, s2, evF[0], evJ[0]);
    cudaStreamWaitEvent(0, evPre, 0);
    run_level(pHn, false, hPhi, hPlo, N1, N2, cPhi2, cPlo2, wPhi2, b2,
              pG, pcnq2, prmax, psinv, GThi, tT,
              pHn, hPhi, hPlo, s2, evF[1], evJ[1]);
    run_level(pHn, false, hPhi, hPlo, N2, N3, cPhi3, cPlo3, wPhi3, b3,
              pG, pcnq3, prmax, psinv, GThi, tT,
              out, nullptr, nullptr, s2, evF[2], evJ[2]);
}